// round 14
// baseline (speedup 1.0000x reference)
#include <cuda_runtime.h>
#include <cuda_fp16.h>

#define BS 4
#define NQ 1024
#define NK 1024
#define QD 128
#define VD 128
#define HID 64
#define NP 32                   // half2 h-pairs

#define TQ 8                    // queries per score block
#define TK 128                  // keys per score tile
#define SC_THREADS 256

__device__ unsigned g_qp  [BS * NQ * NP];   // [b][q][p]  half2(q_{2p}, q_{2p+1})
__device__ unsigned g_kp  [BS * NP * NK];   // [b][p][k]  half2(k_{2p}, k_{2p+1})
__device__ __half   g_vhT [BS * VD * NK];   // [b][n][k]  fp16 V transposed
__device__ __half   g_ph  [BS * NQ * NK];   // [b][q][k]  fp16 exp(s), unnormalized
__device__ float    g_sinv[BS * NQ];        // 1/sum per row

__device__ __forceinline__ unsigned tanh2(unsigned x) {
    unsigned y;
    asm("tanh.approx.f16x2 %0, %1;" : "=r"(y) : "r"(x));
    return y;
}

__device__ __forceinline__ void mma16816(float& d0, float& d1, float& d2, float& d3,
                                         unsigned a0, unsigned a1, unsigned a2, unsigned a3,
                                         unsigned b0, unsigned b1) {
    asm("mma.sync.aligned.m16n8k16.row.col.f32.f16.f16.f32 "
        "{%0,%1,%2,%3}, {%4,%5,%6,%7}, {%8,%9}, {%0,%1,%2,%3};"
        : "+f"(d0), "+f"(d1), "+f"(d2), "+f"(d3)
        : "r"(a0), "r"(a1), "r"(a2), "r"(a3), "r"(b0), "r"(b1));
}

__device__ __forceinline__ void cp16(void* dst, const void* src) {
    unsigned d = (unsigned)__cvta_generic_to_shared(dst);
    asm volatile("cp.async.cg.shared.global [%0], [%1], 16;" :: "r"(d), "l"(src));
}
__device__ __forceinline__ void cp_commit() {
    asm volatile("cp.async.commit_group;");
}
template<int N> __device__ __forceinline__ void cp_wait() {
    asm volatile("cp.async.wait_group %0;" :: "n"(N));
}

// ---------------------------------------------------------------------------
// V transpose + fp16:  g_vhT[b][n][k] = (half) values[b][k][n]
// ---------------------------------------------------------------------------
__global__ __launch_bounds__(256) void vt_kernel(const float* __restrict__ values)
{
    __shared__ float tile[32][33];
    int b  = blockIdx.z;
    int k0 = blockIdx.x * 32;
    int n0 = blockIdx.y * 32;
    int t  = threadIdx.x;
    int r  = t >> 5, c = t & 31;

    const float* vb = values + (size_t)b * NK * VD;
    #pragma unroll
    for (int i = 0; i < 4; ++i)
        tile[r + 8 * i][c] = vb[(size_t)(k0 + r + 8 * i) * VD + n0 + c];
    __syncthreads();
    #pragma unroll
    for (int i = 0; i < 4; ++i) {
        int n = n0 + r + 8 * i;
        g_vhT[((size_t)b * VD + n) * NK + k0 + c] = __float2half_rn(tile[c][r + 8 * i]);
    }
}

// ---------------------------------------------------------------------------
// Projection: natural [d][h] W layout (conflict-free), 32 rows/block.
// ---------------------------------------------------------------------------
#define PJR 32
__global__ __launch_bounds__(256) void proj_kernel(
    const float* __restrict__ queries, const float* __restrict__ keys,
    const float* __restrict__ W_q, const float* __restrict__ W_k)
{
    __shared__ float Ws[QD * HID];      // natural layout, linear copy (32 KB)
    __shared__ float xs[PJR * QD];      // 16 KB

    int bid   = blockIdx.x;
    int which = bid >> 7;               // 0 = q, 1 = k
    int tile  = bid & 127;
    int b     = tile >> 5;
    int r0    = (tile & 31) * PJR;

    const float* X = which ? keys : queries;
    const float* W = which ? W_k  : W_q;
    int t = threadIdx.x;

    for (int i = t; i < QD * HID; i += 256) Ws[i] = W[i];
    const float* xbase = X + ((size_t)b * NQ + r0) * QD;
    for (int i = t; i < PJR * QD; i += 256) xs[i] = xbase[i];
    __syncthreads();

    int h  = t & 63;
    int rg = t >> 6;
    float acc[8] = {0.f, 0.f, 0.f, 0.f, 0.f, 0.f, 0.f, 0.f};
    #pragma unroll 4
    for (int d = 0; d < QD; d += 4) {
        float w0 = Ws[(d + 0) * HID + h];
        float w1 = Ws[(d + 1) * HID + h];
        float w2 = Ws[(d + 2) * HID + h];
        float w3 = Ws[(d + 3) * HID + h];
        #pragma unroll
        for (int i = 0; i < 8; ++i) {
            float4 x4 = *(const float4*)&xs[(rg + 4 * i) * QD + d];
            acc[i] = fmaf(w0, x4.x, fmaf(w1, x4.y,
                     fmaf(w2, x4.z, fmaf(w3, x4.w, acc[i]))));
        }
    }

    int p = h >> 1;
    #pragma unroll
    for (int i = 0; i < 8; ++i) {
        float partner = __shfl_xor_sync(0xffffffffu, acc[i], 1);
        if ((h & 1) == 0) {
            __half2 h2 = __halves2half2(__float2half_rn(acc[i]),
                                        __float2half_rn(partner));
            int r = r0 + rg + 4 * i;
            if (which == 0)
                g_qp[((size_t)b * NQ + r) * NP + p] = *(unsigned*)&h2;
            else
                g_kp[((size_t)b * NP + p) * NK + r] = *(unsigned*)&h2;
        }
    }
}

// ---------------------------------------------------------------------------
// Score kernel: tanh scores -> exp -> fp16 p + 1/sum.
// k read DIRECTLY from gmem (L2-resident, 8-warp reuse per line):
// no smem staging, no cp.async, no hot-loop barriers.
// ---------------------------------------------------------------------------
__global__ __launch_bounds__(SC_THREADS, 4) void score_kernel(
    const float* __restrict__ w_v)
{
    __shared__ unsigned wp[NP];

    int t    = threadIdx.x;
    int b    = blockIdx.y;
    int q0   = blockIdx.x * TQ;
    int qi   = t >> 5;                      // query row = warp
    int lane = t & 31;

    if (t < NP) {
        __half2 h2 = __halves2half2(__float2half_rn(w_v[2 * t]),
                                    __float2half_rn(w_v[2 * t + 1]));
        wp[t] = *(unsigned*)&h2;
    }

    // Query pairs -> registers (reused across all 1024 keys)
    unsigned qreg[NP];
    {
        const uint4* qp4 = (const uint4*)(g_qp + ((size_t)b * NQ + q0 + qi) * NP);
        #pragma unroll
        for (int g = 0; g < NP / 4; ++g) {
            uint4 v = qp4[g];
            qreg[4 * g + 0] = v.x; qreg[4 * g + 1] = v.y;
            qreg[4 * g + 2] = v.z; qreg[4 * g + 3] = v.w;
        }
    }
    __syncthreads();                        // wp visible; only barrier in kernel

    // k base for this thread's 4 keys within each tile
    const unsigned* kpb = g_kp + (size_t)b * NP * NK;
    __half* prow = g_ph + ((size_t)b * NQ + q0 + qi) * NK;
    const __half2 hzero = __float2half2_rn(0.f);
    float sum = 0.f;

    for (int kt = 0; kt < NK / TK; ++kt) {
        const uint4* kb = (const uint4*)(kpb + kt * TK + 4 * lane);   // + p*NK/4 per pair

        float acc[4] = {0.f, 0.f, 0.f, 0.f};
        #pragma unroll
        for (int pg = 0; pg < 4; ++pg) {
            __half2 hacc[4] = {hzero, hzero, hzero, hzero};
            #pragma unroll
            for (int pp = 0; pp < 8; ++pp) {
                int pidx = pg * 8 + pp;
                uint4 kv = kb[(size_t)pidx * (NK / 4)];   // LDG.128, L2 hit
                unsigned qw = qreg[pidx];
                __half2 q2 = *(__half2*)&qw;
                unsigned wv = wp[pidx];                   // broadcast LDS
                __half2 w2 = *(__half2*)&wv;
                unsigned kk[4] = {kv.x, kv.y, kv.z, kv.w};
                #pragma unroll
                for (int j = 0; j < 4; ++j) {
                    __half2 s = __hadd2(q2, *(__half2*)&kk[j]);
                    unsigned tt = tanh2(*(unsigned*)&s);
                    hacc[j] = __hfma2(w2, *(__half2*)&tt, hacc[j]);
                }
            }
            #pragma unroll
            for (int j = 0; j < 4; ++j) {
                float2 f = __half22float2(hacc[j]);
                acc[j] += f.x + f.y;
            }
        }

        float e0 = __expf(acc[0]);
        float e1 = __expf(acc[1]);
        float e2 = __expf(acc[2]);
        float e3 = __expf(acc[3]);
        sum += (e0 + e1) + (e2 + e3);
        __half2 p01 = __floats2half2_rn(e0, e1);
        __half2 p23 = __floats2half2_rn(e2, e3);
        uint2 pu;
        pu.x = *(unsigned*)&p01;
        pu.y = *(unsigned*)&p23;
        *(uint2*)(prow + kt * TK + 4 * lane) = pu;
    }

    #pragma unroll
    for (int o = 16; o > 0; o >>= 1) sum += __shfl_xor_sync(0xffffffffu, sum, o);
    if (lane == 0) g_sinv[b * NQ + q0 + qi] = 1.f / sum;
}

// ---------------------------------------------------------------------------
// PV kernel: out = (P * sinv) @ V via HMMA. N-split (32q x 64cols, grid 256),
// triple-buffered cp.async, one barrier per chunk.  (UNCHANGED from R13)
// ---------------------------------------------------------------------------
#define PVM 32
#define PVN 64
#define PH_ST 136
#define VT_ST 136
#define PV_PH_HALVES (PVM * PH_ST)
#define PV_VT_HALVES (PVN * VT_ST)
#define PV_BUF_HALVES (PV_PH_HALVES + PV_VT_HALVES)
#define PV_SMEM_BYTES (3 * PV_BUF_HALVES * 2)

__global__ __launch_bounds__(256) void pv_kernel(float* __restrict__ out)
{
    extern __shared__ __half pvsm[];

    int t     = threadIdx.x;
    int b     = blockIdx.y;
    int m0    = (blockIdx.x >> 1) * PVM;
    int n0    = (blockIdx.x & 1) * PVN;
    int w     = t >> 5;
    int lane  = t & 31;
    int g     = lane >> 2;
    int t4    = lane & 3;

    int rbase = (w >= 4) ? 16 : 0;
    int cbase = 16 * (w & 3);

    const __half* phb = g_ph  + ((size_t)b * NQ + m0) * NK;
    const __half* vTb = g_vhT + ((size_t)b * VD + n0) * NK;

    auto stage = [&](int ch) {
        __half* buf = pvsm + (ch % 3) * PV_BUF_HALVES;
        __half* phs = buf;
        __half* vss = buf + PV_PH_HALVES;
        int k0 = ch * 128;
        #pragma unroll
        for (int i = 0; i < 2; ++i) {
            int e = t + 256 * i;
            int r = e >> 4, j = e & 15;
            cp16(phs + r * PH_ST + 8 * j, phb + (size_t)r * NK + k0 + 8 * j);
        }
        #pragma unroll
        for (int i = 0; i < 4; ++i) {
            int e = t + 256 * i;
            int r = e >> 4, j = e & 15;
            cp16(vss + r * VT_ST + 8 * j, vTb + (size_t)r * NK + k0 + 8 * j);
        }
    };

    float c[2][4];
    #pragma unroll
    for (int nt = 0; nt < 2; ++nt)
        #pragma unroll
        for (int i = 0; i < 4; ++i) c[nt][i] = 0.f;

    stage(0); cp_commit();
    stage(1); cp_commit();

    for (int ch = 0; ch < 8; ++ch) {
        if (ch < 7) cp_wait<1>(); else cp_wait<0>();
        __syncthreads();

        const __half* buf  = pvsm + (ch % 3) * PV_BUF_HALVES;
        const __half* ph_s = buf;
        const __half* vst  = buf + PV_PH_HALVES;
        #pragma unroll
        for (int ks = 0; ks < 8; ++ks) {
            int kk = 16 * ks;
            unsigned a0 = *(const unsigned*)(ph_s + (rbase + g)     * PH_ST + kk + 2 * t4);
            unsigned a1 = *(const unsigned*)(ph_s + (rbase + g + 8) * PH_ST + kk + 2 * t4);
            unsigned a2 = *(const unsigned*)(ph_s + (rbase + g)     * PH_ST + kk + 8 + 2 * t4);
            unsigned a3 = *(const unsigned*)(ph_s + (rbase + g + 8) * PH_ST + kk + 8 + 2 * t4);
            #pragma unroll
            for (int nt = 0; nt < 2; ++nt) {
                int n = cbase + 8 * nt + g;
                unsigned b0 = *(const unsigned*)(vst + n * VT_ST + kk + 2 * t4);
                unsigned b1 = *(const unsigned*)(vst + n * VT_ST + kk + 8 + 2 * t4);
                mma16816(c[nt][0], c[nt][1], c[nt][2], c[nt][3],
                         a0, a1, a2, a3, b0, b1);
            }
        }

        if (ch < 6) { stage(ch + 2); cp_commit(); }
    }

    int row0 = m0 + rbase + g;
    int row1 = row0 + 8;
    float s0 = g_sinv[b * NQ + row0];
    float s1 = g_sinv[b * NQ + row1];
    float* ob0 = out + ((size_t)b * NQ + row0) * VD + n0;
    float* ob1 = out + ((size_t)b * NQ + row1) * VD + n0;
    #pragma unroll
    for (int nt = 0; nt < 2; ++nt) {
        int col = cbase + 8 * nt + 2 * t4;
        *(float2*)&ob0[col] = make_float2(c[nt][0] * s0, c[nt][1] * s0);
        *(float2*)&ob1[col] = make_float2(c[nt][2] * s1, c[nt][3] * s1);
    }
}

// ---------------------------------------------------------------------------
extern "C" void kernel_launch(void* const* d_in, const int* in_sizes, int n_in,
                              void* d_out, int out_size)
{
    const float* queries = (const float*)d_in[0];
    const float* keys    = (const float*)d_in[1];
    const float* values  = (const float*)d_in[2];
    const float* W_q     = (const float*)d_in[3];
    const float* W_k     = (const float*)d_in[4];
    const float* w_v     = (const float*)d_in[5];
    float* out = (float*)d_out;

    cudaFuncSetAttribute(pv_kernel, cudaFuncAttributeMaxDynamicSharedMemorySize,
                         PV_SMEM_BYTES);

    vt_kernel<<<dim3(NK / 32, VD / 32, BS), 256>>>(values);
    proj_kernel<<<256, 256>>>(queries, keys, W_q, W_k);
    score_kernel<<<dim3(NQ / TQ, BS), SC_THREADS>>>(w_v);
    pv_kernel<<<dim3((NQ / PVM) * 2, BS), 256, PV_SMEM_BYTES>>>(out);
}

// round 15
// speedup vs baseline: 1.0355x; 1.0355x over previous
#include <cuda_runtime.h>
#include <cuda_fp16.h>

#define BS 4
#define NQ 1024
#define NK 1024
#define QD 128
#define VD 128
#define HID 64
#define NP 32                   // half2 h-pairs

#define TQ 8                    // queries per score block
#define TK 128                  // keys per score tile
#define SC_THREADS 256
#define KSH_WORDS (NP * TK)
#define SC_SMEM_BYTES ((3 * KSH_WORDS + NP) * 4)

__device__ unsigned g_qp  [BS * NQ * NP];   // [b][q][p]  half2(q_{2p}, q_{2p+1})
__device__ unsigned g_kp  [BS * NP * NK];   // [b][p][k]  half2(k_{2p}, k_{2p+1})
__device__ __half   g_vhT [BS * VD * NK];   // [b][n][k]  fp16 V transposed
__device__ __half   g_ph  [BS * NQ * NK];   // [b][q][k]  fp16 exp(s), unnormalized
__device__ float    g_sinv[BS * NQ];        // 1/sum per row

__device__ __forceinline__ unsigned tanh2(unsigned x) {
    unsigned y;
    asm("tanh.approx.f16x2 %0, %1;" : "=r"(y) : "r"(x));
    return y;
}

__device__ __forceinline__ void mma16816(float& d0, float& d1, float& d2, float& d3,
                                         unsigned a0, unsigned a1, unsigned a2, unsigned a3,
                                         unsigned b0, unsigned b1) {
    asm("mma.sync.aligned.m16n8k16.row.col.f32.f16.f16.f32 "
        "{%0,%1,%2,%3}, {%4,%5,%6,%7}, {%8,%9}, {%0,%1,%2,%3};"
        : "+f"(d0), "+f"(d1), "+f"(d2), "+f"(d3)
        : "r"(a0), "r"(a1), "r"(a2), "r"(a3), "r"(b0), "r"(b1));
}

__device__ __forceinline__ void ldsm_x4(unsigned& r0, unsigned& r1,
                                        unsigned& r2, unsigned& r3, unsigned addr) {
    asm volatile("ldmatrix.sync.aligned.m8n8.x4.shared.b16 {%0,%1,%2,%3}, [%4];"
                 : "=r"(r0), "=r"(r1), "=r"(r2), "=r"(r3) : "r"(addr));
}

__device__ __forceinline__ void cp16(void* dst, const void* src) {
    unsigned d = (unsigned)__cvta_generic_to_shared(dst);
    asm volatile("cp.async.cg.shared.global [%0], [%1], 16;" :: "r"(d), "l"(src));
}
__device__ __forceinline__ void cp_commit() {
    asm volatile("cp.async.commit_group;");
}
template<int N> __device__ __forceinline__ void cp_wait() {
    asm volatile("cp.async.wait_group %0;" :: "n"(N));
}

// ---------------------------------------------------------------------------
// V transpose + fp16:  g_vhT[b][n][k] = (half) values[b][k][n]
// ---------------------------------------------------------------------------
__global__ __launch_bounds__(256) void vt_kernel(const float* __restrict__ values)
{
    __shared__ float tile[32][33];
    int b  = blockIdx.z;
    int k0 = blockIdx.x * 32;
    int n0 = blockIdx.y * 32;
    int t  = threadIdx.x;
    int r  = t >> 5, c = t & 31;

    const float* vb = values + (size_t)b * NK * VD;
    #pragma unroll
    for (int i = 0; i < 4; ++i)
        tile[r + 8 * i][c] = vb[(size_t)(k0 + r + 8 * i) * VD + n0 + c];
    __syncthreads();
    #pragma unroll
    for (int i = 0; i < 4; ++i) {
        int n = n0 + r + 8 * i;
        g_vhT[((size_t)b * VD + n) * NK + k0 + c] = __float2half_rn(tile[c][r + 8 * i]);
    }
}

// ---------------------------------------------------------------------------
// Projection: natural [d][h] W layout (conflict-free), 32 rows/block.
// ---------------------------------------------------------------------------
#define PJR 32
__global__ __launch_bounds__(256) void proj_kernel(
    const float* __restrict__ queries, const float* __restrict__ keys,
    const float* __restrict__ W_q, const float* __restrict__ W_k)
{
    __shared__ float Ws[QD * HID];      // natural layout, linear copy (32 KB)
    __shared__ float xs[PJR * QD];      // 16 KB

    int bid   = blockIdx.x;
    int which = bid >> 7;               // 0 = q, 1 = k
    int tile  = bid & 127;
    int b     = tile >> 5;
    int r0    = (tile & 31) * PJR;

    const float* X = which ? keys : queries;
    const float* W = which ? W_k  : W_q;
    int t = threadIdx.x;

    for (int i = t; i < QD * HID; i += 256) Ws[i] = W[i];
    const float* xbase = X + ((size_t)b * NQ + r0) * QD;
    for (int i = t; i < PJR * QD; i += 256) xs[i] = xbase[i];
    __syncthreads();

    int h  = t & 63;
    int rg = t >> 6;
    float acc[8] = {0.f, 0.f, 0.f, 0.f, 0.f, 0.f, 0.f, 0.f};
    #pragma unroll 4
    for (int d = 0; d < QD; d += 4) {
        float w0 = Ws[(d + 0) * HID + h];
        float w1 = Ws[(d + 1) * HID + h];
        float w2 = Ws[(d + 2) * HID + h];
        float w3 = Ws[(d + 3) * HID + h];
        #pragma unroll
        for (int i = 0; i < 8; ++i) {
            float4 x4 = *(const float4*)&xs[(rg + 4 * i) * QD + d];
            acc[i] = fmaf(w0, x4.x, fmaf(w1, x4.y,
                     fmaf(w2, x4.z, fmaf(w3, x4.w, acc[i]))));
        }
    }

    int p = h >> 1;
    #pragma unroll
    for (int i = 0; i < 8; ++i) {
        float partner = __shfl_xor_sync(0xffffffffu, acc[i], 1);
        if ((h & 1) == 0) {
            __half2 h2 = __halves2half2(__float2half_rn(acc[i]),
                                        __float2half_rn(partner));
            int r = r0 + rg + 4 * i;
            if (which == 0)
                g_qp[((size_t)b * NQ + r) * NP + p] = *(unsigned*)&h2;
            else
                g_kp[((size_t)b * NP + p) * NK + r] = *(unsigned*)&h2;
        }
    }
}

// ---------------------------------------------------------------------------
// Score kernel (R13, reverted): tanh scores -> exp -> fp16 p + 1/sum.
// Triple-buffered cp.async, one barrier per tile.
// ---------------------------------------------------------------------------
__global__ __launch_bounds__(SC_THREADS, 4) void score_kernel(
    const float* __restrict__ w_v)
{
    extern __shared__ unsigned scsm[];
    unsigned* ksh = scsm;                   // 3 x [NP][TK]
    unsigned* wp  = scsm + 3 * KSH_WORDS;   // [NP]

    int t    = threadIdx.x;
    int b    = blockIdx.y;
    int q0   = blockIdx.x * TQ;
    int qi   = t >> 5;                      // query row = warp
    int lane = t & 31;

    if (t < NP) {
        __half2 h2 = __halves2half2(__float2half_rn(w_v[2 * t]),
                                    __float2half_rn(w_v[2 * t + 1]));
        wp[t] = *(unsigned*)&h2;
    }

    unsigned qreg[NP];
    {
        const uint4* qp4 = (const uint4*)(g_qp + ((size_t)b * NQ + q0 + qi) * NP);
        #pragma unroll
        for (int g = 0; g < NP / 4; ++g) {
            uint4 v = qp4[g];
            qreg[4 * g + 0] = v.x; qreg[4 * g + 1] = v.y;
            qreg[4 * g + 2] = v.z; qreg[4 * g + 3] = v.w;
        }
    }

    const unsigned* kpb = g_kp + (size_t)b * NP * NK;
    auto stage = [&](int kt) {
        unsigned* dst = ksh + (kt % 3) * KSH_WORDS;
        #pragma unroll
        for (int r = 0; r < 4; ++r) {
            int e4 = t + 256 * r;
            int p = e4 >> 5, k4 = e4 & 31;
            cp16(dst + p * TK + 4 * k4, kpb + (size_t)p * NK + kt * TK + 4 * k4);
        }
    };

    stage(0); cp_commit();
    stage(1); cp_commit();

    __half* prow = g_ph + ((size_t)b * NQ + q0 + qi) * NK;
    const __half2 hzero = __float2half2_rn(0.f);
    float sum = 0.f;

    for (int kt = 0; kt < NK / TK; ++kt) {
        if (kt < 7) cp_wait<1>(); else cp_wait<0>();
        __syncthreads();

        const unsigned* kb = ksh + (kt % 3) * KSH_WORDS;
        float acc[4] = {0.f, 0.f, 0.f, 0.f};
        #pragma unroll
        for (int pg = 0; pg < 4; ++pg) {
            __half2 hacc[4] = {hzero, hzero, hzero, hzero};
            #pragma unroll
            for (int pp = 0; pp < 8; ++pp) {
                int pidx = pg * 8 + pp;
                uint4 kv = *(const uint4*)&kb[pidx * TK + 4 * lane];
                unsigned qw = qreg[pidx];
                __half2 q2 = *(__half2*)&qw;
                unsigned wv = wp[pidx];                 // broadcast LDS
                __half2 w2 = *(__half2*)&wv;
                unsigned kk[4] = {kv.x, kv.y, kv.z, kv.w};
                #pragma unroll
                for (int j = 0; j < 4; ++j) {
                    __half2 s = __hadd2(q2, *(__half2*)&kk[j]);
                    unsigned tt = tanh2(*(unsigned*)&s);
                    hacc[j] = __hfma2(w2, *(__half2*)&tt, hacc[j]);
                }
            }
            #pragma unroll
            for (int j = 0; j < 4; ++j) {
                float2 f = __half22float2(hacc[j]);
                acc[j] += f.x + f.y;
            }
        }

        float e0 = __expf(acc[0]);
        float e1 = __expf(acc[1]);
        float e2 = __expf(acc[2]);
        float e3 = __expf(acc[3]);
        sum += (e0 + e1) + (e2 + e3);
        __half2 p01 = __floats2half2_rn(e0, e1);
        __half2 p23 = __floats2half2_rn(e2, e3);
        uint2 pu;
        pu.x = *(unsigned*)&p01;
        pu.y = *(unsigned*)&p23;
        *(uint2*)(prow + kt * TK + 4 * lane) = pu;

        if (kt < 6) { stage(kt + 2); cp_commit(); }
    }

    #pragma unroll
    for (int o = 16; o > 0; o >>= 1) sum += __shfl_xor_sync(0xffffffffu, sum, o);
    if (lane == 0) g_sinv[b * NQ + q0 + qi] = 1.f / sum;
}

// ---------------------------------------------------------------------------
// PV kernel: out = (P * sinv) @ V via HMMA. N-split (32q x 64cols, grid 256),
// triple-buffered cp.async; fragments loaded via ldmatrix.x4 (LDSM).
// ---------------------------------------------------------------------------
#define PVM 32
#define PVN 64
#define PH_ST 136
#define VT_ST 136
#define PV_PH_HALVES (PVM * PH_ST)
#define PV_VT_HALVES (PVN * VT_ST)
#define PV_BUF_HALVES (PV_PH_HALVES + PV_VT_HALVES)
#define PV_SMEM_BYTES (3 * PV_BUF_HALVES * 2)

__global__ __launch_bounds__(256) void pv_kernel(float* __restrict__ out)
{
    extern __shared__ __half pvsm[];

    int t     = threadIdx.x;
    int b     = blockIdx.y;
    int m0    = (blockIdx.x >> 1) * PVM;
    int n0    = (blockIdx.x & 1) * PVN;
    int w     = t >> 5;
    int lane  = t & 31;
    int g     = lane >> 2;
    int t4    = lane & 3;

    int rbase = (w >= 4) ? 16 : 0;
    int cbase = 16 * (w & 3);

    const __half* phb = g_ph  + ((size_t)b * NQ + m0) * NK;
    const __half* vTb = g_vhT + ((size_t)b * VD + n0) * NK;

    auto stage = [&](int ch) {
        __half* buf = pvsm + (ch % 3) * PV_BUF_HALVES;
        __half* phs = buf;
        __half* vss = buf + PV_PH_HALVES;
        int k0 = ch * 128;
        #pragma unroll
        for (int i = 0; i < 2; ++i) {
            int e = t + 256 * i;
            int r = e >> 4, j = e & 15;
            cp16(phs + r * PH_ST + 8 * j, phb + (size_t)r * NK + k0 + 8 * j);
        }
        #pragma unroll
        for (int i = 0; i < 4; ++i) {
            int e = t + 256 * i;
            int r = e >> 4, j = e & 15;
            cp16(vss + r * VT_ST + 8 * j, vTb + (size_t)r * NK + k0 + 8 * j);
        }
    };

    // Per-lane ldmatrix base offsets (in halves, within a buffer)
    // A (x4): m8n8 matrices 0/1 = rows rbase+0..15 @k, 2/3 = same rows @k+8
    unsigned a_off = (unsigned)((rbase + (lane & 15)) * PH_ST + ((lane >> 4) << 3));
    // B (x4): matrices 0/1 = nt0 (n = cbase+0..7) k/k+8, 2/3 = nt1 (n+8)
    unsigned b_off = (unsigned)(PV_PH_HALVES
                   + (cbase + (lane & 7) + ((lane >> 4) << 3)) * VT_ST
                   + (((lane >> 3) & 1) << 3));
    unsigned smem_base = (unsigned)__cvta_generic_to_shared(pvsm);

    float c[2][4];
    #pragma unroll
    for (int nt = 0; nt < 2; ++nt)
        #pragma unroll
        for (int i = 0; i < 4; ++i) c[nt][i] = 0.f;

    stage(0); cp_commit();
    stage(1); cp_commit();

    for (int ch = 0; ch < 8; ++ch) {
        if (ch < 7) cp_wait<1>(); else cp_wait<0>();
        __syncthreads();

        unsigned bufb = smem_base + (unsigned)((ch % 3) * PV_BUF_HALVES) * 2u;
        unsigned a_addr = bufb + a_off * 2u;
        unsigned b_addr = bufb + b_off * 2u;
        #pragma unroll
        for (int ks = 0; ks < 8; ++ks) {
            unsigned a0, a1, a2, a3, b0n0, b1n0, b0n1, b1n1;
            ldsm_x4(a0, a1, a2, a3, a_addr + 32u * ks);
            ldsm_x4(b0n0, b1n0, b0n1, b1n1, b_addr + 32u * ks);
            mma16816(c[0][0], c[0][1], c[0][2], c[0][3], a0, a1, a2, a3, b0n0, b1n0);
            mma16816(c[1][0], c[1][1], c[1][2], c[1][3], a0, a1, a2, a3, b0n1, b1n1);
        }

        if (ch < 6) { stage(ch + 2); cp_commit(); }
    }

    int row0 = m0 + rbase + g;
    int row1 = row0 + 8;
    float s0 = g_sinv[b * NQ + row0];
    float s1 = g_sinv[b * NQ + row1];
    float* ob0 = out + ((size_t)b * NQ + row0) * VD + n0;
    float* ob1 = out + ((size_t)b * NQ + row1) * VD + n0;
    #pragma unroll
    for (int nt = 0; nt < 2; ++nt) {
        int col = cbase + 8 * nt + 2 * t4;
        *(float2*)&ob0[col] = make_float2(c[nt][0] * s0, c[nt][1] * s0);
        *(float2*)&ob1[col] = make_float2(c[nt][2] * s1, c[nt][3] * s1);
    }
}

// ---------------------------------------------------------------------------
extern "C" void kernel_launch(void* const* d_in, const int* in_sizes, int n_in,
                              void* d_out, int out_size)
{
    const float* queries = (const float*)d_in[0];
    const float* keys    = (const float*)d_in[1];
    const float* values  = (const float*)d_in[2];
    const float* W_q     = (const float*)d_in[3];
    const float* W_k     = (const float*)d_in[4];
    const float* w_v     = (const float*)d_in[5];
    float* out = (float*)d_out;

    cudaFuncSetAttribute(score_kernel, cudaFuncAttributeMaxDynamicSharedMemorySize,
                         SC_SMEM_BYTES);
    cudaFuncSetAttribute(pv_kernel, cudaFuncAttributeMaxDynamicSharedMemorySize,
                         PV_SMEM_BYTES);

    vt_kernel<<<dim3(NK / 32, VD / 32, BS), 256>>>(values);
    proj_kernel<<<256, 256>>>(queries, keys, W_q, W_k);
    score_kernel<<<dim3(NQ / TQ, BS), SC_THREADS, SC_SMEM_BYTES>>>(w_v);
    pv_kernel<<<dim3((NQ / PVM) * 2, BS), 256, PV_SMEM_BYTES>>>(out);
}